// round 5
// baseline (speedup 1.0000x reference)
#include <cuda_runtime.h>
#include <cstdint>

#define Dd 1024
#define Bb 32
#define Ss 2048
#define Mtot (Bb * Ss)          // 65536
#define M_TILE 128
#define N_TILE 128
#define K_TILE 32
#define NSTG 3
#define NTILES (Dd / N_TILE)    // 8
#define NCHUNK (Dd / K_TILE)    // 32

#define A_STRIDE 36             // floats; conflict-free, 16B-aligned rows
#define B_STRIDE 136

#define OFF_HQ   0
#define OFF_V    512
#define STAGE_BYTES (M_TILE * A_STRIDE * 4 + K_TILE * B_STRIDE * 4)  // 35840
#define OFF_A(s) (1024 + (s) * STAGE_BYTES)
#define OFF_B(s) (OFF_A(s) + M_TILE * A_STRIDE * 4)
#define SMEM_BYTES (1024 + NSTG * STAGE_BYTES)   // 108544

__device__ float g_Hq[Bb * Dd];
__device__ float g_Wt[Dd * Dd];                  // tf32-rounded bottom W (4 MB)
__device__ float g_partial[NTILES * Mtot];       // 2 MB

__device__ __forceinline__ float tanh_fast(float x) {
    float y; asm("tanh.approx.f32 %0, %1;" : "=f"(y) : "f"(x)); return y;
}
__device__ __forceinline__ float rna_tf32(float x) {
    float y; asm("cvt.rna.tf32.f32 %0, %1;" : "=f"(y) : "f"(x)); return y;
}
__device__ __forceinline__ uint32_t ld_tf32(const float* p) {
    return __float_as_uint(rna_tf32(*p));
}
__device__ __forceinline__ void mma_tf32(float (&d)[4], const uint32_t (&a)[4],
                                         const uint32_t (&b)[2]) {
    asm volatile(
        "mma.sync.aligned.m16n8k8.row.col.f32.tf32.tf32.f32 "
        "{%0,%1,%2,%3}, {%4,%5,%6,%7}, {%8,%9}, {%0,%1,%2,%3};"
        : "+f"(d[0]), "+f"(d[1]), "+f"(d[2]), "+f"(d[3])
        : "r"(a[0]), "r"(a[1]), "r"(a[2]), "r"(a[3]), "r"(b[0]), "r"(b[1]));
}
__device__ __forceinline__ void cp_async16(uint32_t dst, const void* src) {
    asm volatile("cp.async.cg.shared.global [%0], [%1], 16;"
                 :: "r"(dst), "l"(src) : "memory");
}
__device__ __forceinline__ void cp_commit() {
    asm volatile("cp.async.commit_group;" ::: "memory");
}
__device__ __forceinline__ void cp_wait1() {
    asm volatile("cp.async.wait_group 1;" ::: "memory");
}
__device__ __forceinline__ uint32_t smem_u32(const void* p) {
    uint32_t a;
    asm("{ .reg .u64 t; cvta.to.shared.u64 t, %1; cvt.u32.u64 %0, t; }"
        : "=r"(a) : "l"(p));
    return a;
}

// ---------------------------------------------------------------------------
// Kernel 0: g_Wt = tf32_rna(W_bottom)   (grid 1024, block 256)
// ---------------------------------------------------------------------------
__global__ void wconv_kernel(const float* __restrict__ W) {
    const float* Wb = W + (size_t)Dd * Dd;
    const int i = (blockIdx.x * 256 + threadIdx.x) * 4;
    float4 x = *reinterpret_cast<const float4*>(Wb + i);
    x.x = rna_tf32(x.x); x.y = rna_tf32(x.y);
    x.z = rna_tf32(x.z); x.w = rna_tf32(x.w);
    *reinterpret_cast<float4*>(g_Wt + i) = x;
}

// ---------------------------------------------------------------------------
// Kernel 1: Hq[b,n] = bias[n] + sum_k hidden[b,k]*W[k,n]  (top half of W)
// ---------------------------------------------------------------------------
__global__ void prep_kernel(const float* __restrict__ hidden,
                            const float* __restrict__ W,
                            const float* __restrict__ bias) {
    __shared__ float h[Dd];
    __shared__ float red[256];
    const int b = blockIdx.y;
    const int n0 = blockIdx.x * 32;
    const int t = threadIdx.x;
    {
        float4 v4 = *reinterpret_cast<const float4*>(hidden + b * Dd + t * 4);
        h[t * 4 + 0] = v4.x; h[t * 4 + 1] = v4.y;
        h[t * 4 + 2] = v4.z; h[t * 4 + 3] = v4.w;
    }
    __syncthreads();
    const int n = n0 + (t & 31);
    const int kbeg = (t >> 5) * 128;
    float acc = 0.f;
#pragma unroll 8
    for (int k = kbeg; k < kbeg + 128; k++)
        acc = fmaf(h[k], W[(size_t)k * Dd + n], acc);
    red[t] = acc;
    __syncthreads();
    if (t < 32) {
        float s = bias[n0 + t];
#pragma unroll
        for (int j = 0; j < 8; j++) s += red[j * 32 + t];
        g_Hq[b * Dd + n0 + t] = s;
    }
}

// ---------------------------------------------------------------------------
// Kernel 2: pipelined tf32 GEMM (8 warps of 32x64, 2 CTA/SM) + fused epilogue
// grid (8, 512), block 256
// ---------------------------------------------------------------------------
__global__ __launch_bounds__(256, 2)
void gemm_tanh_kernel(const float* __restrict__ E,
                      const float* __restrict__ v) {
    extern __shared__ __align__(1024) char smem[];
    const uint32_t sb = smem_u32(smem);

    const int tid = threadIdx.x;
    const int wid = tid >> 5;
    const int lane = tid & 31;
    const int g = lane >> 2;
    const int tig = lane & 3;
    const int warp_m = wid & 3;     // 4 warps along M (32 rows each)
    const int warp_n = wid >> 2;    // 2 warps along N (64 cols each)

    const int n0 = blockIdx.x * N_TILE;
    const int m0 = blockIdx.y * M_TILE;
    const int b = blockIdx.y >> 4;

    float* hq_s = reinterpret_cast<float*>(smem + OFF_HQ);
    float* v_s  = reinterpret_cast<float*>(smem + OFF_V);
    if (tid < N_TILE) {
        hq_s[tid] = g_Hq[b * Dd + n0 + tid];
        v_s[tid]  = v[n0 + tid];
    }

    auto issue_stage = [&](int i) {
        const int kt = i * K_TILE;
        const int s = i % NSTG;
        const uint32_t abase = sb + OFF_A(s);
        const uint32_t bbase = sb + OFF_B(s);
#pragma unroll
        for (int p = 0; p < 4; p++) {
            int id = tid + p * 256;
            int row = id >> 3, ch = id & 7;
            cp_async16(abase + row * (A_STRIDE * 4) + ch * 16,
                       E + (size_t)(m0 + row) * Dd + kt + ch * 4);
        }
#pragma unroll
        for (int p = 0; p < 4; p++) {
            int id = tid + p * 256;
            int row = id >> 5, ch = id & 31;
            cp_async16(bbase + row * (B_STRIDE * 4) + ch * 16,
                       g_Wt + (size_t)(kt + row) * Dd + n0 + ch * 4);
        }
        cp_commit();
    };

    issue_stage(0);
    issue_stage(1);

    float acc[2][8][4];
#pragma unroll
    for (int mf = 0; mf < 2; mf++)
#pragma unroll
        for (int nf = 0; nf < 8; nf++)
#pragma unroll
            for (int i = 0; i < 4; i++) acc[mf][nf][i] = 0.f;

    for (int i = 0; i < NCHUNK; i++) {
        cp_wait1();
        __syncthreads();
        if (i + 2 < NCHUNK) issue_stage(i + 2);

        const int s = i % NSTG;
        const float* As = reinterpret_cast<const float*>(smem + OFF_A(s));
        const float* Bs = reinterpret_cast<const float*>(smem + OFF_B(s));

#pragma unroll
        for (int kk = 0; kk < K_TILE; kk += 8) {
            uint32_t afrag[2][4], bfrag[8][2];
#pragma unroll
            for (int mf = 0; mf < 2; mf++) {
                const int r0 = warp_m * 32 + mf * 16 + g;
                afrag[mf][0] = ld_tf32(&As[r0 * A_STRIDE + kk + tig]);
                afrag[mf][1] = ld_tf32(&As[(r0 + 8) * A_STRIDE + kk + tig]);
                afrag[mf][2] = ld_tf32(&As[r0 * A_STRIDE + kk + tig + 4]);
                afrag[mf][3] = ld_tf32(&As[(r0 + 8) * A_STRIDE + kk + tig + 4]);
            }
#pragma unroll
            for (int nf = 0; nf < 8; nf++) {
                const int c = warp_n * 64 + nf * 8 + g;
                bfrag[nf][0] = __float_as_uint(Bs[(kk + tig) * B_STRIDE + c]);
                bfrag[nf][1] = __float_as_uint(Bs[(kk + tig + 4) * B_STRIDE + c]);
            }
#pragma unroll
            for (int mf = 0; mf < 2; mf++)
#pragma unroll
                for (int nf = 0; nf < 8; nf++)
                    mma_tf32(acc[mf][nf], afrag[mf], bfrag[nf]);
        }
        __syncthreads();
    }

    // ---- epilogue: tanh + v-weighted row reduction ----
    float hq[16], vv[16];
#pragma unroll
    for (int nf = 0; nf < 8; nf++)
#pragma unroll
        for (int j = 0; j < 2; j++) {
            const int c = warp_n * 64 + nf * 8 + 2 * tig + j;
            hq[nf * 2 + j] = hq_s[c];
            vv[nf * 2 + j] = v_s[c];
        }

    float psum[4] = {0.f, 0.f, 0.f, 0.f};
#pragma unroll
    for (int mf = 0; mf < 2; mf++)
#pragma unroll
        for (int nf = 0; nf < 8; nf++)
#pragma unroll
            for (int i = 0; i < 4; i++) {
                const int half = i >> 1;
                const int j = i & 1;
                float e = tanh_fast(acc[mf][nf][i] + hq[nf * 2 + j]);
                psum[mf * 2 + half] = fmaf(e, vv[nf * 2 + j], psum[mf * 2 + half]);
            }
#pragma unroll
    for (int r = 0; r < 4; r++) {
        psum[r] += __shfl_xor_sync(0xffffffffu, psum[r], 1);
        psum[r] += __shfl_xor_sync(0xffffffffu, psum[r], 2);
    }

    __syncthreads();
    float* sums = reinterpret_cast<float*>(smem + OFF_A(0));
    if (tig == 0) {
#pragma unroll
        for (int r = 0; r < 4; r++) {
            const int mf = r >> 1, half = r & 1;
            const int lrow = warp_m * 32 + mf * 16 + half * 8 + g;
            sums[lrow * 2 + warp_n] = psum[r];
        }
    }
    __syncthreads();
    if (tid < M_TILE)
        g_partial[(size_t)blockIdx.x * Mtot + m0 + tid] =
            sums[tid * 2] + sums[tid * 2 + 1];
}

// ---------------------------------------------------------------------------
// Kernel 3: sum partials, mask, softmax per batch row
// ---------------------------------------------------------------------------
__global__ void softmax_kernel(const int* __restrict__ src_len,
                               float* __restrict__ out) {
    const int b = blockIdx.x;
    const int len = src_len[b];
    const int tid = threadIdx.x;
    __shared__ float sc[Ss];
    __shared__ float red[256];

    float lmax = -3.0e38f;
    for (int s = tid; s < Ss; s += 256) {
        float val = 0.f;
#pragma unroll
        for (int t = 0; t < NTILES; t++)
            val += g_partial[(size_t)t * Mtot + b * Ss + s];
        if (s >= len) val = -3.0e38f;
        sc[s] = val;
        lmax = fmaxf(lmax, val);
    }
    red[tid] = lmax;
    __syncthreads();
    for (int o = 128; o > 0; o >>= 1) {
        if (tid < o) red[tid] = fmaxf(red[tid], red[tid + o]);
        __syncthreads();
    }
    const float gmax = red[0];
    __syncthreads();

    float lsum = 0.f;
    for (int s = tid; s < Ss; s += 256) {
        float e = (s < len) ? __expf(sc[s] - gmax) : 0.f;
        sc[s] = e;
        lsum += e;
    }
    red[tid] = lsum;
    __syncthreads();
    for (int o = 128; o > 0; o >>= 1) {
        if (tid < o) red[tid] += red[tid + o];
        __syncthreads();
    }
    const float inv = 1.f / red[0];
    __syncthreads();
    for (int s = tid; s < Ss; s += 256) out[b * Ss + s] = sc[s] * inv;
}

// ---------------------------------------------------------------------------
extern "C" void kernel_launch(void* const* d_in, const int* in_sizes, int n_in,
                              void* d_out, int out_size) {
    const float* hidden  = (const float*)d_in[0];
    const float* enc     = (const float*)d_in[1];
    const float* W       = (const float*)d_in[2];
    const float* bias    = (const float*)d_in[3];
    const float* v       = (const float*)d_in[4];
    const int*   src_len = (const int*)d_in[5];
    float* out = (float*)d_out;

    cudaFuncSetAttribute(gemm_tanh_kernel,
                         cudaFuncAttributeMaxDynamicSharedMemorySize, SMEM_BYTES);

    wconv_kernel<<<1024, 256>>>(W);
    prep_kernel<<<dim3(32, 32), 256>>>(hidden, W, bias);
    gemm_tanh_kernel<<<dim3(NTILES, Mtot / M_TILE), 256, SMEM_BYTES>>>(enc, v);
    softmax_kernel<<<Bb, 256>>>(src_len, out);
}

// round 7
// speedup vs baseline: 1.6964x; 1.6964x over previous
#include <cuda_runtime.h>
#include <cuda_fp16.h>
#include <cstdint>

#define Dd 1024
#define Bb 32
#define Ss 2048
#define Mtot (Bb * Ss)          // 65536
#define M_TILE 128
#define N_TILE 128
#define K_TILE 64               // fp16 elems per stage
#define NSTG 3
#define NTILES (Dd / N_TILE)    // 8
#define NCHUNK (Dd / K_TILE)    // 16

#define ROW_BYTES 144           // 64 fp16 = 128B data + 16B pad (conflict-free)

#define OFF_HQ   0
#define OFF_V    512
#define STAGE_BYTES (M_TILE * ROW_BYTES + N_TILE * ROW_BYTES)   // 36864
#define OFF_A(s) (1024 + (s) * STAGE_BYTES)
#define OFF_B(s) (OFF_A(s) + M_TILE * ROW_BYTES)
#define SMEM_BYTES (1024 + NSTG * STAGE_BYTES)                   // 111616

__device__ float g_Hq[Bb * Dd];
__device__ __half g_Ehf[(size_t)Mtot * Dd];   // 128 MB
__device__ __half g_WhfT[Dd * Dd];            // 2 MB, [n][k]
__device__ float g_partial[NTILES * Mtot];    // 2 MB

__device__ __forceinline__ float tanh_fast(float x) {
    float y; asm("tanh.approx.f32 %0, %1;" : "=f"(y) : "f"(x)); return y;
}
__device__ __forceinline__ uint32_t pack_f16x2(float lo, float hi) {
    __half2 h = __floats2half2_rn(lo, hi);
    return *reinterpret_cast<uint32_t*>(&h);
}
__device__ __forceinline__ void mma_f16(float (&d)[4], const uint32_t (&a)[4],
                                        const uint32_t (&b)[2]) {
    asm volatile(
        "mma.sync.aligned.m16n8k16.row.col.f32.f16.f16.f32 "
        "{%0,%1,%2,%3}, {%4,%5,%6,%7}, {%8,%9}, {%0,%1,%2,%3};"
        : "+f"(d[0]), "+f"(d[1]), "+f"(d[2]), "+f"(d[3])
        : "r"(a[0]), "r"(a[1]), "r"(a[2]), "r"(a[3]), "r"(b[0]), "r"(b[1]));
}
__device__ __forceinline__ void cp_async16(uint32_t dst, const void* src) {
    asm volatile("cp.async.cg.shared.global [%0], [%1], 16;"
                 :: "r"(dst), "l"(src) : "memory");
}
__device__ __forceinline__ void cp_commit() {
    asm volatile("cp.async.commit_group;" ::: "memory");
}
__device__ __forceinline__ void cp_wait1() {
    asm volatile("cp.async.wait_group 1;" ::: "memory");
}
__device__ __forceinline__ uint32_t smem_u32(const void* p) {
    uint32_t a;
    asm("{ .reg .u64 t; cvta.to.shared.u64 t, %1; cvt.u32.u64 %0, t; }"
        : "=r"(a) : "l"(p));
    return a;
}
__device__ __forceinline__ uint32_t lds32(const char* base, int byteoff) {
    return *reinterpret_cast<const uint32_t*>(base + byteoff);
}

// ---------------------------------------------------------------------------
// Kernel 0a: E (fp32) -> g_Ehf (fp16). 8 elems/thread. grid 32768, block 256.
// ---------------------------------------------------------------------------
__global__ void econv_kernel(const float* __restrict__ E) {
    const size_t i = ((size_t)blockIdx.x * 256 + threadIdx.x) * 8;
    float4 x0 = *reinterpret_cast<const float4*>(E + i);
    float4 x1 = *reinterpret_cast<const float4*>(E + i + 4);
    uint4 o;
    o.x = pack_f16x2(x0.x, x0.y);
    o.y = pack_f16x2(x0.z, x0.w);
    o.z = pack_f16x2(x1.x, x1.y);
    o.w = pack_f16x2(x1.z, x1.w);
    *reinterpret_cast<uint4*>(&g_Ehf[i]) = o;
}

// ---------------------------------------------------------------------------
// Kernel 0b: W bottom [k][n] fp32 -> g_WhfT [n][k] fp16 (transpose+convert)
// grid (32, 32), block (32, 8)
// ---------------------------------------------------------------------------
__global__ void wconvT_kernel(const float* __restrict__ W) {
    __shared__ float tile[32][33];
    const float* Wb = W + (size_t)Dd * Dd;
    const int kt = blockIdx.x * 32;
    const int nt = blockIdx.y * 32;
    const int tx = threadIdx.x, ty = threadIdx.y;
#pragma unroll
    for (int i = 0; i < 4; i++)
        tile[ty + 8 * i][tx] = Wb[(size_t)(kt + ty + 8 * i) * Dd + nt + tx];
    __syncthreads();
#pragma unroll
    for (int i = 0; i < 4; i++)
        g_WhfT[(size_t)(nt + ty + 8 * i) * Dd + kt + tx] =
            __float2half_rn(tile[tx][ty + 8 * i]);
}

// ---------------------------------------------------------------------------
// Kernel 1: Hq[b,n] = bias[n] + sum_k hidden[b,k]*W[k,n]  (top half, fp32 exact)
// ---------------------------------------------------------------------------
__global__ void prep_kernel(const float* __restrict__ hidden,
                            const float* __restrict__ W,
                            const float* __restrict__ bias) {
    __shared__ float h[Dd];
    __shared__ float red[256];
    const int b = blockIdx.y;
    const int n0 = blockIdx.x * 32;
    const int t = threadIdx.x;
    {
        float4 v4 = *reinterpret_cast<const float4*>(hidden + b * Dd + t * 4);
        h[t * 4 + 0] = v4.x; h[t * 4 + 1] = v4.y;
        h[t * 4 + 2] = v4.z; h[t * 4 + 3] = v4.w;
    }
    __syncthreads();
    const int n = n0 + (t & 31);
    const int kbeg = (t >> 5) * 128;
    float acc = 0.f;
#pragma unroll 8
    for (int k = kbeg; k < kbeg + 128; k++)
        acc = fmaf(h[k], W[(size_t)k * Dd + n], acc);
    red[t] = acc;
    __syncthreads();
    if (t < 32) {
        float s = bias[n0 + t];
#pragma unroll
        for (int j = 0; j < 8; j++) s += red[j * 32 + t];
        g_Hq[b * Dd + n0 + t] = s;
    }
}

// ---------------------------------------------------------------------------
// Kernel 2: pipelined fp16 GEMM (4 warps of 64x64, 2 CTA/SM) + fused epilogue
// grid (8, 512), block 128
// ---------------------------------------------------------------------------
__global__ __launch_bounds__(128, 2)
void gemm_tanh_kernel(const float* __restrict__ v) {
    extern __shared__ __align__(1024) char smem[];
    const uint32_t sb = smem_u32(smem);

    const int tid = threadIdx.x;
    const int wid = tid >> 5;
    const int lane = tid & 31;
    const int g = lane >> 2;
    const int tig = lane & 3;
    const int warp_m = wid & 1;        // 2 warps along M (64 rows each)
    const int warp_n = wid >> 1;       // 2 warps along N (64 cols each)

    const int n0 = blockIdx.x * N_TILE;
    const int m0 = blockIdx.y * M_TILE;
    const int b = blockIdx.y >> 4;

    float* hq_s = reinterpret_cast<float*>(smem + OFF_HQ);
    float* v_s  = reinterpret_cast<float*>(smem + OFF_V);
    hq_s[tid] = g_Hq[b * Dd + n0 + tid];
    v_s[tid]  = v[n0 + tid];

    auto issue_stage = [&](int i) {
        const int kt = i * K_TILE;
        const int s = i % NSTG;
        const uint32_t abase = sb + OFF_A(s);
        const uint32_t bbase = sb + OFF_B(s);
#pragma unroll
        for (int p = 0; p < 8; p++) {
            int id = tid + p * 128;               // 0..1023
            int row = id >> 3, ch = id & 7;       // 8 chunks of 16B per row
            cp_async16(abase + row * ROW_BYTES + ch * 16,
                       &g_Ehf[(size_t)(m0 + row) * Dd + kt + ch * 8]);
        }
#pragma unroll
        for (int p = 0; p < 8; p++) {
            int id = tid + p * 128;
            int row = id >> 3, ch = id & 7;
            cp_async16(bbase + row * ROW_BYTES + ch * 16,
                       &g_WhfT[(size_t)(n0 + row) * Dd + kt + ch * 8]);
        }
        cp_commit();
    };

    issue_stage(0);
    issue_stage(1);

    float acc[4][8][4];
#pragma unroll
    for (int mf = 0; mf < 4; mf++)
#pragma unroll
        for (int nf = 0; nf < 8; nf++)
#pragma unroll
            for (int i = 0; i < 4; i++) acc[mf][nf][i] = 0.f;

    for (int i = 0; i < NCHUNK; i++) {
        cp_wait1();
        __syncthreads();
        if (i + 2 < NCHUNK) issue_stage(i + 2);

        const int s = i % NSTG;
        const char* As = smem + OFF_A(s);
        const char* Bs = smem + OFF_B(s);

#pragma unroll
        for (int kk = 0; kk < 4; kk++) {          // 4 x k16 steps
            const int kb = kk * 32;               // byte offset of k-block (16 fp16)
            uint32_t afrag[4][4], bfrag[8][2];
#pragma unroll
            for (int mf = 0; mf < 4; mf++) {
                const int r0 = warp_m * 64 + mf * 16 + g;
                const int base0 = r0 * ROW_BYTES + kb + tig * 4;
                const int base1 = (r0 + 8) * ROW_BYTES + kb + tig * 4;
                afrag[mf][0] = lds32(As, base0);
                afrag[mf][1] = lds32(As, base1);
                afrag[mf][2] = lds32(As, base0 + 16);
                afrag[mf][3] = lds32(As, base1 + 16);
            }
#pragma unroll
            for (int nf = 0; nf < 8; nf++) {
                const int n = warp_n * 64 + nf * 8 + g;
                const int base = n * ROW_BYTES + kb + tig * 4;
                bfrag[nf][0] = lds32(Bs, base);
                bfrag[nf][1] = lds32(Bs, base + 16);
            }
#pragma unroll
            for (int mf = 0; mf < 4; mf++)
#pragma unroll
                for (int nf = 0; nf < 8; nf++)
                    mma_f16(acc[mf][nf], afrag[mf], bfrag[nf]);
        }
        __syncthreads();
    }

    // ---- epilogue: tanh + v-weighted row reduction ----
    float hq[16], vv[16];
#pragma unroll
    for (int nf = 0; nf < 8; nf++)
#pragma unroll
        for (int j = 0; j < 2; j++) {
            const int c = warp_n * 64 + nf * 8 + 2 * tig + j;
            hq[nf * 2 + j] = hq_s[c];
            vv[nf * 2 + j] = v_s[c];
        }

    float psum[8];
#pragma unroll
    for (int r = 0; r < 8; r++) psum[r] = 0.f;
#pragma unroll
    for (int mf = 0; mf < 4; mf++)
#pragma unroll
        for (int nf = 0; nf < 8; nf++)
#pragma unroll
            for (int i = 0; i < 4; i++) {
                const int half = i >> 1;
                const int j = i & 1;
                float e = tanh_fast(acc[mf][nf][i] + hq[nf * 2 + j]);
                psum[mf * 2 + half] = fmaf(e, vv[nf * 2 + j], psum[mf * 2 + half]);
            }
#pragma unroll
    for (int r = 0; r < 8; r++) {
        psum[r] += __shfl_xor_sync(0xffffffffu, psum[r], 1);
        psum[r] += __shfl_xor_sync(0xffffffffu, psum[r], 2);
    }

    __syncthreads();
    float* sums = reinterpret_cast<float*>(smem + OFF_A(0));
    if (tig == 0) {
#pragma unroll
        for (int r = 0; r < 8; r++) {
            const int mf = r >> 1, half = r & 1;
            const int lrow = warp_m * 64 + mf * 16 + half * 8 + g;
            sums[lrow * 2 + warp_n] = psum[r];
        }
    }
    __syncthreads();
    g_partial[(size_t)blockIdx.x * Mtot + m0 + tid] =
        sums[tid * 2] + sums[tid * 2 + 1];
}

// ---------------------------------------------------------------------------
// Kernel 3: sum partials, mask, softmax per batch row
// ---------------------------------------------------------------------------
__global__ void softmax_kernel(const int* __restrict__ src_len,
                               float* __restrict__ out) {
    const int b = blockIdx.x;
    const int len = src_len[b];
    const int tid = threadIdx.x;
    __shared__ float sc[Ss];
    __shared__ float red[256];

    float lmax = -3.0e38f;
    for (int s = tid; s < Ss; s += 256) {
        float val = 0.f;
#pragma unroll
        for (int t = 0; t < NTILES; t++)
            val += g_partial[(size_t)t * Mtot + b * Ss + s];
        if (s >= len) val = -3.0e38f;
        sc[s] = val;
        lmax = fmaxf(lmax, val);
    }
    red[tid] = lmax;
    __syncthreads();
    for (int o = 128; o > 0; o >>= 1) {
        if (tid < o) red[tid] = fmaxf(red[tid], red[tid + o]);
        __syncthreads();
    }
    const float gmax = red[0];
    __syncthreads();

    float lsum = 0.f;
    for (int s = tid; s < Ss; s += 256) {
        float e = (s < len) ? __expf(sc[s] - gmax) : 0.f;
        sc[s] = e;
        lsum += e;
    }
    red[tid] = lsum;
    __syncthreads();
    for (int o = 128; o > 0; o >>= 1) {
        if (tid < o) red[tid] += red[tid + o];
        __syncthreads();
    }
    const float inv = 1.f / red[0];
    __syncthreads();
    for (int s = tid; s < Ss; s += 256) out[b * Ss + s] = sc[s] * inv;
}

// ---------------------------------------------------------------------------
extern "C" void kernel_launch(void* const* d_in, const int* in_sizes, int n_in,
                              void* d_out, int out_size) {
    const float* hidden  = (const float*)d_in[0];
    const float* enc     = (const float*)d_in[1];
    const float* W       = (const float*)d_in[2];
    const float* bias    = (const float*)d_in[3];
    const float* v       = (const float*)d_in[4];
    const int*   src_len = (const int*)d_in[5];
    float* out = (float*)d_out;

    cudaFuncSetAttribute(gemm_tanh_kernel,
                         cudaFuncAttributeMaxDynamicSharedMemorySize, SMEM_BYTES);

    econv_kernel<<<32768, 256>>>(enc);
    wconvT_kernel<<<dim3(32, 32), dim3(32, 8)>>>(W);
    prep_kernel<<<dim3(32, 32), 256>>>(hidden, W, bias);
    gemm_tanh_kernel<<<dim3(NTILES, Mtot / M_TILE), 128, SMEM_BYTES>>>(v);
    softmax_kernel<<<Bb, 256>>>(src_len, out);
}

// round 8
// speedup vs baseline: 1.7661x; 1.0411x over previous
#include <cuda_runtime.h>
#include <cuda_fp16.h>
#include <cstdint>

#define Dd 1024
#define Bb 32
#define Ss 2048
#define Mtot (Bb * Ss)          // 65536
#define M_TILE 128
#define N_TILE 128
#define K_TILE 64               // fp16 elems per stage
#define NSTG 3
#define NTILES (Dd / N_TILE)    // 8
#define NCHUNK (Dd / K_TILE)    // 16

#define ROW_BYTES 144           // 64 fp16 = 128B data + 16B pad (conflict-free)

#define OFF_HQ   0
#define OFF_V    512
#define STAGE_BYTES (M_TILE * ROW_BYTES + N_TILE * ROW_BYTES)   // 36864
#define OFF_A(s) (1024 + (s) * STAGE_BYTES)
#define OFF_B(s) (OFF_A(s) + M_TILE * ROW_BYTES)
#define SMEM_BYTES (1024 + NSTG * STAGE_BYTES)                   // 111616

__device__ float g_Hq[Bb * Dd];
__device__ __half g_Ehf[(size_t)Mtot * Dd];   // 128 MB
__device__ __half g_WhfT[Dd * Dd];            // 2 MB, [n][k]
__device__ float g_partial[NTILES * Mtot];    // 2 MB

__device__ __forceinline__ float tanh_fast(float x) {
    float y; asm("tanh.approx.f32 %0, %1;" : "=f"(y) : "f"(x)); return y;
}
__device__ __forceinline__ uint32_t pack_f16x2(float lo, float hi) {
    __half2 h = __floats2half2_rn(lo, hi);
    return *reinterpret_cast<uint32_t*>(&h);
}
__device__ __forceinline__ void mma_f16(float (&d)[4], const uint32_t (&a)[4],
                                        const uint32_t (&b)[2]) {
    asm volatile(
        "mma.sync.aligned.m16n8k16.row.col.f32.f16.f16.f32 "
        "{%0,%1,%2,%3}, {%4,%5,%6,%7}, {%8,%9}, {%0,%1,%2,%3};"
        : "+f"(d[0]), "+f"(d[1]), "+f"(d[2]), "+f"(d[3])
        : "r"(a[0]), "r"(a[1]), "r"(a[2]), "r"(a[3]), "r"(b[0]), "r"(b[1]));
}
__device__ __forceinline__ void ldmatrix_x4(uint32_t& r0, uint32_t& r1,
                                            uint32_t& r2, uint32_t& r3,
                                            uint32_t addr) {
    asm volatile("ldmatrix.sync.aligned.m8n8.x4.shared.b16 {%0,%1,%2,%3}, [%4];"
                 : "=r"(r0), "=r"(r1), "=r"(r2), "=r"(r3) : "r"(addr));
}
__device__ __forceinline__ void cp_async16(uint32_t dst, const void* src) {
    asm volatile("cp.async.cg.shared.global [%0], [%1], 16;"
                 :: "r"(dst), "l"(src) : "memory");
}
__device__ __forceinline__ void cp_commit() {
    asm volatile("cp.async.commit_group;" ::: "memory");
}
__device__ __forceinline__ void cp_wait1() {
    asm volatile("cp.async.wait_group 1;" ::: "memory");
}
__device__ __forceinline__ uint32_t smem_u32(const void* p) {
    uint32_t a;
    asm("{ .reg .u64 t; cvta.to.shared.u64 t, %1; cvt.u32.u64 %0, t; }"
        : "=r"(a) : "l"(p));
    return a;
}

// ---------------------------------------------------------------------------
// Kernel 0a: E (fp32) -> g_Ehf (fp16). 8 elems/thread.
// ---------------------------------------------------------------------------
__global__ void econv_kernel(const float* __restrict__ E) {
    const size_t i = ((size_t)blockIdx.x * 256 + threadIdx.x) * 8;
    float4 x0 = *reinterpret_cast<const float4*>(E + i);
    float4 x1 = *reinterpret_cast<const float4*>(E + i + 4);
    uint4 o;
    o.x = pack_f16x2(x0.x, x0.y);
    o.y = pack_f16x2(x0.z, x0.w);
    o.z = pack_f16x2(x1.x, x1.y);
    o.w = pack_f16x2(x1.z, x1.w);
    *reinterpret_cast<uint4*>(&g_Ehf[i]) = o;
}

// ---------------------------------------------------------------------------
// Kernel 0b: W bottom [k][n] fp32 -> g_WhfT [n][k] fp16 (transpose+convert)
// ---------------------------------------------------------------------------
__global__ void wconvT_kernel(const float* __restrict__ W) {
    __shared__ float tile[32][33];
    const float* Wb = W + (size_t)Dd * Dd;
    const int kt = blockIdx.x * 32;
    const int nt = blockIdx.y * 32;
    const int tx = threadIdx.x, ty = threadIdx.y;
#pragma unroll
    for (int i = 0; i < 4; i++)
        tile[ty + 8 * i][tx] = Wb[(size_t)(kt + ty + 8 * i) * Dd + nt + tx];
    __syncthreads();
#pragma unroll
    for (int i = 0; i < 4; i++)
        g_WhfT[(size_t)(nt + ty + 8 * i) * Dd + kt + tx] =
            __float2half_rn(tile[tx][ty + 8 * i]);
}

// ---------------------------------------------------------------------------
// Kernel 1: Hq[b,n] = bias[n] + sum_k hidden[b,k]*W[k,n]  (top half, fp32 exact)
// ---------------------------------------------------------------------------
__global__ void prep_kernel(const float* __restrict__ hidden,
                            const float* __restrict__ W,
                            const float* __restrict__ bias) {
    __shared__ float h[Dd];
    __shared__ float red[256];
    const int b = blockIdx.y;
    const int n0 = blockIdx.x * 32;
    const int t = threadIdx.x;
    {
        float4 v4 = *reinterpret_cast<const float4*>(hidden + b * Dd + t * 4);
        h[t * 4 + 0] = v4.x; h[t * 4 + 1] = v4.y;
        h[t * 4 + 2] = v4.z; h[t * 4 + 3] = v4.w;
    }
    __syncthreads();
    const int n = n0 + (t & 31);
    const int kbeg = (t >> 5) * 128;
    float acc = 0.f;
#pragma unroll 8
    for (int k = kbeg; k < kbeg + 128; k++)
        acc = fmaf(h[k], W[(size_t)k * Dd + n], acc);
    red[t] = acc;
    __syncthreads();
    if (t < 32) {
        float s = bias[n0 + t];
#pragma unroll
        for (int j = 0; j < 8; j++) s += red[j * 32 + t];
        g_Hq[b * Dd + n0 + t] = s;
    }
}

// ---------------------------------------------------------------------------
// Kernel 2: pipelined fp16 GEMM (ldmatrix fragments) + fused epilogue
// grid (8, 512), block 128, 2 CTA/SM
// ---------------------------------------------------------------------------
__global__ __launch_bounds__(128, 2)
void gemm_tanh_kernel(const float* __restrict__ v) {
    extern __shared__ __align__(1024) char smem[];
    const uint32_t sb = smem_u32(smem);

    const int tid = threadIdx.x;
    const int wid = tid >> 5;
    const int lane = tid & 31;
    const int g = lane >> 2;
    const int tig = lane & 3;
    const int warp_m = wid & 1;        // 2 warps along M (64 rows each)
    const int warp_n = wid >> 1;       // 2 warps along N (64 cols each)

    const int n0 = blockIdx.x * N_TILE;
    const int m0 = blockIdx.y * M_TILE;
    const int b = blockIdx.y >> 4;

    float* hq_s = reinterpret_cast<float*>(smem + OFF_HQ);
    float* v_s  = reinterpret_cast<float*>(smem + OFF_V);
    hq_s[tid] = g_Hq[b * Dd + n0 + tid];
    v_s[tid]  = v[n0 + tid];

    // ldmatrix per-lane address offsets (relative to stage tile base)
    // A (x4 per mf): rows m = warp_m*64+mf*16 + (lane&7) + ((lane>>3)&1)*8,
    //                k-byte = (lane>>4)*16
    uint32_t aoff[4], boff[4];
#pragma unroll
    for (int mf = 0; mf < 4; mf++) {
        int row = warp_m * 64 + mf * 16 + (lane & 7) + ((lane >> 3) & 1) * 8;
        aoff[mf] = row * ROW_BYTES + ((lane >> 4) & 1) * 16;
    }
    // B (x4 per np covering nf=2np,2np+1):
    //   n = warp_n*64 + np*16 + (lane&7) + (lane>>4)*8, k-byte = ((lane>>3)&1)*16
#pragma unroll
    for (int np = 0; np < 4; np++) {
        int row = warp_n * 64 + np * 16 + (lane & 7) + ((lane >> 4) & 1) * 8;
        boff[np] = row * ROW_BYTES + ((lane >> 3) & 1) * 16;
    }

    auto issue_stage = [&](int i) {
        const int kt = i * K_TILE;
        const int s = i % NSTG;
        const uint32_t abase = sb + OFF_A(s);
        const uint32_t bbase = sb + OFF_B(s);
#pragma unroll
        for (int p = 0; p < 8; p++) {
            int id = tid + p * 128;               // 0..1023
            int row = id >> 3, ch = id & 7;
            cp_async16(abase + row * ROW_BYTES + ch * 16,
                       &g_Ehf[(size_t)(m0 + row) * Dd + kt + ch * 8]);
        }
#pragma unroll
        for (int p = 0; p < 8; p++) {
            int id = tid + p * 128;
            int row = id >> 3, ch = id & 7;
            cp_async16(bbase + row * ROW_BYTES + ch * 16,
                       &g_WhfT[(size_t)(n0 + row) * Dd + kt + ch * 8]);
        }
        cp_commit();
    };

    issue_stage(0);
    issue_stage(1);

    float acc[4][8][4];
#pragma unroll
    for (int mf = 0; mf < 4; mf++)
#pragma unroll
        for (int nf = 0; nf < 8; nf++)
#pragma unroll
            for (int i = 0; i < 4; i++) acc[mf][nf][i] = 0.f;

    for (int i = 0; i < NCHUNK; i++) {
        cp_wait1();
        __syncthreads();
        if (i + 2 < NCHUNK) issue_stage(i + 2);

        const int s = i % NSTG;
        const uint32_t As = sb + OFF_A(s);
        const uint32_t Bs = sb + OFF_B(s);

#pragma unroll
        for (int kk = 0; kk < 4; kk++) {          // 4 x k16 steps
            const int kb = kk * 32;               // byte offset of 16-elem k-block
            uint32_t afrag[4][4], bfrag[8][2];
#pragma unroll
            for (int mf = 0; mf < 4; mf++)
                ldmatrix_x4(afrag[mf][0], afrag[mf][1], afrag[mf][2], afrag[mf][3],
                            As + aoff[mf] + kb);
#pragma unroll
            for (int np = 0; np < 4; np++)
                ldmatrix_x4(bfrag[2 * np][0], bfrag[2 * np][1],
                            bfrag[2 * np + 1][0], bfrag[2 * np + 1][1],
                            Bs + boff[np] + kb);
#pragma unroll
            for (int mf = 0; mf < 4; mf++)
#pragma unroll
                for (int nf = 0; nf < 8; nf++)
                    mma_f16(acc[mf][nf], afrag[mf], bfrag[nf]);
        }
        __syncthreads();
    }

    // ---- epilogue: tanh + v-weighted row reduction ----
    float hq[16], vv[16];
#pragma unroll
    for (int nf = 0; nf < 8; nf++)
#pragma unroll
        for (int j = 0; j < 2; j++) {
            const int c = warp_n * 64 + nf * 8 + 2 * tig + j;
            hq[nf * 2 + j] = hq_s[c];
            vv[nf * 2 + j] = v_s[c];
        }

    float psum[8];
#pragma unroll
    for (int r = 0; r < 8; r++) psum[r] = 0.f;
#pragma unroll
    for (int mf = 0; mf < 4; mf++)
#pragma unroll
        for (int nf = 0; nf < 8; nf++)
#pragma unroll
            for (int i = 0; i < 4; i++) {
                const int half = i >> 1;
                const int j = i & 1;
                float e = tanh_fast(acc[mf][nf][i] + hq[nf * 2 + j]);
                psum[mf * 2 + half] = fmaf(e, vv[nf * 2 + j], psum[mf * 2 + half]);
            }
#pragma unroll
    for (int r = 0; r < 8; r++) {
        psum[r] += __shfl_xor_sync(0xffffffffu, psum[r], 1);
        psum[r] += __shfl_xor_sync(0xffffffffu, psum[r], 2);
    }

    __syncthreads();
    float* sums = reinterpret_cast<float*>(smem + OFF_A(0));
    if (tig == 0) {
#pragma unroll
        for (int r = 0; r < 8; r++) {
            const int mf = r >> 1, half = r & 1;
            const int lrow = warp_m * 64 + mf * 16 + half * 8 + g;
            sums[lrow * 2 + warp_n] = psum[r];
        }
    }
    __syncthreads();
    g_partial[(size_t)blockIdx.x * Mtot + m0 + tid] =
        sums[tid * 2] + sums[tid * 2 + 1];
}

// ---------------------------------------------------------------------------
// Kernel 3: sum partials, mask, softmax per batch row
// ---------------------------------------------------------------------------
__global__ void softmax_kernel(const int* __restrict__ src_len,
                               float* __restrict__ out) {
    const int b = blockIdx.x;
    const int len = src_len[b];
    const int tid = threadIdx.x;
    __shared__ float sc[Ss];
    __shared__ float red[256];

    float lmax = -3.0e38f;
    for (int s = tid; s < Ss; s += 256) {
        float val = 0.f;
#pragma unroll
        for (int t = 0; t < NTILES; t++)
            val += g_partial[(size_t)t * Mtot + b * Ss + s];
        if (s >= len) val = -3.0e38f;
        sc[s] = val;
        lmax = fmaxf(lmax, val);
    }
    red[tid] = lmax;
    __syncthreads();
    for (int o = 128; o > 0; o >>= 1) {
        if (tid < o) red[tid] = fmaxf(red[tid], red[tid + o]);
        __syncthreads();
    }
    const float gmax = red[0];
    __syncthreads();

    float lsum = 0.f;
    for (int s = tid; s < Ss; s += 256) {
        float e = (s < len) ? __expf(sc[s] - gmax) : 0.f;
        sc[s] = e;
        lsum += e;
    }
    red[tid] = lsum;
    __syncthreads();
    for (int o = 128; o > 0; o >>= 1) {
        if (tid < o) red[tid] += red[tid + o];
        __syncthreads();
    }
    const float inv = 1.f / red[0];
    __syncthreads();
    for (int s = tid; s < Ss; s += 256) out[b * Ss + s] = sc[s] * inv;
}

// ---------------------------------------------------------------------------
extern "C" void kernel_launch(void* const* d_in, const int* in_sizes, int n_in,
                              void* d_out, int out_size) {
    const float* hidden  = (const float*)d_in[0];
    const float* enc     = (const float*)d_in[1];
    const float* W       = (const float*)d_in[2];
    const float* bias    = (const float*)d_in[3];
    const float* v       = (const float*)d_in[4];
    const int*   src_len = (const int*)d_in[5];
    float* out = (float*)d_out;

    cudaFuncSetAttribute(gemm_tanh_kernel,
                         cudaFuncAttributeMaxDynamicSharedMemorySize, SMEM_BYTES);

    econv_kernel<<<32768, 256>>>(enc);
    wconvT_kernel<<<dim3(32, 32), dim3(32, 8)>>>(W);
    prep_kernel<<<dim3(32, 32), 256>>>(hidden, W, bias);
    gemm_tanh_kernel<<<dim3(NTILES, Mtot / M_TILE), 128, SMEM_BYTES>>>(v);
    softmax_kernel<<<Bb, 256>>>(src_len, out);
}

// round 9
// speedup vs baseline: 1.8110x; 1.0254x over previous
#include <cuda_runtime.h>
#include <cuda_fp16.h>
#include <cstdint>

#define Dd 1024
#define Bb 32
#define Ss 2048
#define Mtot (Bb * Ss)          // 65536
#define M_TILE 128
#define N_TILE 128
#define K_TILE 64               // fp16 elems per stage
#define NSTG 3
#define NTILES (Dd / N_TILE)    // 8
#define NCHUNK (Dd / K_TILE)    // 16

#define ROW_BYTES 144           // 64 fp16 = 128B data + 16B pad (conflict-free)

#define OFF_HQ   0
#define OFF_V    512
#define STAGE_BYTES (M_TILE * ROW_BYTES + N_TILE * ROW_BYTES)   // 36864
#define OFF_A(s) (1024 + (s) * STAGE_BYTES)
#define OFF_B(s) (OFF_A(s) + M_TILE * ROW_BYTES)
#define SMEM_BYTES (1024 + NSTG * STAGE_BYTES)                   // 111616

__device__ float g_Hq[Bb * Dd];
__device__ __half g_Ehf[(size_t)Mtot * Dd];   // 128 MB
__device__ __half g_WhfT[Dd * Dd];            // 2 MB, [n][k]
__device__ float g_partial[NTILES * Mtot];    // 2 MB

__device__ __forceinline__ float tanh_fast(float x) {
    float y; asm("tanh.approx.f32 %0, %1;" : "=f"(y) : "f"(x)); return y;
}
__device__ __forceinline__ uint32_t pack_f16x2(float lo, float hi) {
    __half2 h = __floats2half2_rn(lo, hi);
    return *reinterpret_cast<uint32_t*>(&h);
}
__device__ __forceinline__ void mma_f16(float (&d)[4], const uint32_t (&a)[4],
                                        const uint32_t (&b)[2]) {
    asm volatile(
        "mma.sync.aligned.m16n8k16.row.col.f32.f16.f16.f32 "
        "{%0,%1,%2,%3}, {%4,%5,%6,%7}, {%8,%9}, {%0,%1,%2,%3};"
        : "+f"(d[0]), "+f"(d[1]), "+f"(d[2]), "+f"(d[3])
        : "r"(a[0]), "r"(a[1]), "r"(a[2]), "r"(a[3]), "r"(b[0]), "r"(b[1]));
}
__device__ __forceinline__ void ldmatrix_x4(uint32_t& r0, uint32_t& r1,
                                            uint32_t& r2, uint32_t& r3,
                                            uint32_t addr) {
    asm volatile("ldmatrix.sync.aligned.m8n8.x4.shared.b16 {%0,%1,%2,%3}, [%4];"
                 : "=r"(r0), "=r"(r1), "=r"(r2), "=r"(r3) : "r"(addr));
}
__device__ __forceinline__ void cp_async16(uint32_t dst, const void* src) {
    asm volatile("cp.async.cg.shared.global [%0], [%1], 16;"
                 :: "r"(dst), "l"(src) : "memory");
}
__device__ __forceinline__ void cp_commit() {
    asm volatile("cp.async.commit_group;" ::: "memory");
}
__device__ __forceinline__ void cp_wait1() {
    asm volatile("cp.async.wait_group 1;" ::: "memory");
}
__device__ __forceinline__ uint32_t smem_u32(const void* p) {
    uint32_t a;
    asm("{ .reg .u64 t; cvta.to.shared.u64 t, %1; cvt.u32.u64 %0, t; }"
        : "=r"(a) : "l"(p));
    return a;
}

// ---------------------------------------------------------------------------
// Kernel 0a: E (fp32) -> g_Ehf (fp16). 16 elems/thread, streaming stores.
// grid 16384, block 256
// ---------------------------------------------------------------------------
__global__ void econv_kernel(const float* __restrict__ E) {
    const size_t i = ((size_t)blockIdx.x * 256 + threadIdx.x) * 16;
#pragma unroll
    for (int q = 0; q < 2; q++) {
        float4 x0 = __ldg(reinterpret_cast<const float4*>(E + i + q * 8));
        float4 x1 = __ldg(reinterpret_cast<const float4*>(E + i + q * 8 + 4));
        uint4 o;
        o.x = pack_f16x2(x0.x, x0.y);
        o.y = pack_f16x2(x0.z, x0.w);
        o.z = pack_f16x2(x1.x, x1.y);
        o.w = pack_f16x2(x1.z, x1.w);
        __stcs(reinterpret_cast<uint4*>(&g_Ehf[i + q * 8]), o);
    }
}

// ---------------------------------------------------------------------------
// Kernel 0b: W bottom [k][n] fp32 -> g_WhfT [n][k] fp16 (transpose+convert)
// ---------------------------------------------------------------------------
__global__ void wconvT_kernel(const float* __restrict__ W) {
    __shared__ float tile[32][33];
    const float* Wb = W + (size_t)Dd * Dd;
    const int kt = blockIdx.x * 32;
    const int nt = blockIdx.y * 32;
    const int tx = threadIdx.x, ty = threadIdx.y;
#pragma unroll
    for (int i = 0; i < 4; i++)
        tile[ty + 8 * i][tx] = Wb[(size_t)(kt + ty + 8 * i) * Dd + nt + tx];
    __syncthreads();
#pragma unroll
    for (int i = 0; i < 4; i++)
        g_WhfT[(size_t)(nt + ty + 8 * i) * Dd + kt + tx] =
            __float2half_rn(tile[tx][ty + 8 * i]);
}

// ---------------------------------------------------------------------------
// Kernel 1: Hq[b,n] = bias[n] + sum_k hidden[b,k]*W[k,n]  (top half, fp32 exact)
// ---------------------------------------------------------------------------
__global__ void prep_kernel(const float* __restrict__ hidden,
                            const float* __restrict__ W,
                            const float* __restrict__ bias) {
    __shared__ float h[Dd];
    __shared__ float red[256];
    const int b = blockIdx.y;
    const int n0 = blockIdx.x * 32;
    const int t = threadIdx.x;
    {
        float4 v4 = *reinterpret_cast<const float4*>(hidden + b * Dd + t * 4);
        h[t * 4 + 0] = v4.x; h[t * 4 + 1] = v4.y;
        h[t * 4 + 2] = v4.z; h[t * 4 + 3] = v4.w;
    }
    __syncthreads();
    const int n = n0 + (t & 31);
    const int kbeg = (t >> 5) * 128;
    float acc = 0.f;
#pragma unroll 8
    for (int k = kbeg; k < kbeg + 128; k++)
        acc = fmaf(h[k], W[(size_t)k * Dd + n], acc);
    red[t] = acc;
    __syncthreads();
    if (t < 32) {
        float s = bias[n0 + t];
#pragma unroll
        for (int j = 0; j < 8; j++) s += red[j * 32 + t];
        g_Hq[b * Dd + n0 + t] = s;
    }
}

// ---------------------------------------------------------------------------
// Kernel 2: pipelined fp16 GEMM, 8 warps of 64x32, 2 CTA/SM, single-sync loop
// grid (8, 512), block 256
// ---------------------------------------------------------------------------
__global__ __launch_bounds__(256, 2)
void gemm_tanh_kernel(const float* __restrict__ v) {
    extern __shared__ __align__(1024) char smem[];
    const uint32_t sb = smem_u32(smem);

    const int tid = threadIdx.x;
    const int wid = tid >> 5;
    const int lane = tid & 31;
    const int g = lane >> 2;
    const int tig = lane & 3;
    const int warp_m = wid & 1;        // 2 warps along M (64 rows each)
    const int warp_n = wid >> 1;       // 4 warps along N (32 cols each)

    const int n0 = blockIdx.x * N_TILE;
    const int m0 = blockIdx.y * M_TILE;
    const int b = blockIdx.y >> 4;

    float* hq_s = reinterpret_cast<float*>(smem + OFF_HQ);
    float* v_s  = reinterpret_cast<float*>(smem + OFF_V);
    if (tid < N_TILE) {
        hq_s[tid] = g_Hq[b * Dd + n0 + tid];
        v_s[tid]  = v[n0 + tid];
    }

    // ldmatrix per-lane address offsets (relative to stage tile base)
    uint32_t aoff[4], boff[2];
#pragma unroll
    for (int mf = 0; mf < 4; mf++) {
        int row = warp_m * 64 + mf * 16 + (lane & 7) + ((lane >> 3) & 1) * 8;
        aoff[mf] = row * ROW_BYTES + ((lane >> 4) & 1) * 16;
    }
#pragma unroll
    for (int np = 0; np < 2; np++) {
        int row = warp_n * 32 + np * 16 + (lane & 7) + ((lane >> 4) & 1) * 8;
        boff[np] = row * ROW_BYTES + ((lane >> 3) & 1) * 16;
    }

    auto issue_stage = [&](int i) {
        const int kt = i * K_TILE;
        const int s = i % NSTG;
        const uint32_t abase = sb + OFF_A(s);
        const uint32_t bbase = sb + OFF_B(s);
#pragma unroll
        for (int p = 0; p < 4; p++) {
            int id = tid + p * 256;               // 0..1023
            int row = id >> 3, ch = id & 7;
            cp_async16(abase + row * ROW_BYTES + ch * 16,
                       &g_Ehf[(size_t)(m0 + row) * Dd + kt + ch * 8]);
        }
#pragma unroll
        for (int p = 0; p < 4; p++) {
            int id = tid + p * 256;
            int row = id >> 3, ch = id & 7;
            cp_async16(bbase + row * ROW_BYTES + ch * 16,
                       &g_WhfT[(size_t)(n0 + row) * Dd + kt + ch * 8]);
        }
        cp_commit();
    };

    issue_stage(0);
    issue_stage(1);

    float acc[4][4][4];
#pragma unroll
    for (int mf = 0; mf < 4; mf++)
#pragma unroll
        for (int nf = 0; nf < 4; nf++)
#pragma unroll
            for (int i = 0; i < 4; i++) acc[mf][nf][i] = 0.f;

    for (int i = 0; i < NCHUNK; i++) {
        cp_wait1();
        __syncthreads();            // single barrier per iteration (see analysis)
        if (i + 2 < NCHUNK) issue_stage(i + 2);

        const int s = i % NSTG;
        const uint32_t As = sb + OFF_A(s);
        const uint32_t Bs = sb + OFF_B(s);

#pragma unroll
        for (int kk = 0; kk < 4; kk++) {          // 4 x k16 steps
            const int kb = kk * 32;
            uint32_t afrag[4][4], bfrag[4][2];
#pragma unroll
            for (int mf = 0; mf < 4; mf++)
                ldmatrix_x4(afrag[mf][0], afrag[mf][1], afrag[mf][2], afrag[mf][3],
                            As + aoff[mf] + kb);
#pragma unroll
            for (int np = 0; np < 2; np++)
                ldmatrix_x4(bfrag[2 * np][0], bfrag[2 * np][1],
                            bfrag[2 * np + 1][0], bfrag[2 * np + 1][1],
                            Bs + boff[np] + kb);
#pragma unroll
            for (int mf = 0; mf < 4; mf++)
#pragma unroll
                for (int nf = 0; nf < 4; nf++)
                    mma_f16(acc[mf][nf], afrag[mf], bfrag[nf]);
        }
    }
    __syncthreads();

    // ---- epilogue: tanh + v-weighted row reduction ----
    float hq[8], vv[8];
#pragma unroll
    for (int nf = 0; nf < 4; nf++)
#pragma unroll
        for (int j = 0; j < 2; j++) {
            const int c = warp_n * 32 + nf * 8 + 2 * tig + j;
            hq[nf * 2 + j] = hq_s[c];
            vv[nf * 2 + j] = v_s[c];
        }

    float psum[8];
#pragma unroll
    for (int r = 0; r < 8; r++) psum[r] = 0.f;
#pragma unroll
    for (int mf = 0; mf < 4; mf++)
#pragma unroll
        for (int nf = 0; nf < 4; nf++)
#pragma unroll
            for (int i = 0; i < 4; i++) {
                const int half = i >> 1;
                const int j = i & 1;
                float e = tanh_fast(acc[mf][nf][i] + hq[nf * 2 + j]);
                psum[mf * 2 + half] = fmaf(e, vv[nf * 2 + j], psum[mf * 2 + half]);
            }
#pragma unroll
    for (int r = 0; r < 8; r++) {
        psum[r] += __shfl_xor_sync(0xffffffffu, psum[r], 1);
        psum[r] += __shfl_xor_sync(0xffffffffu, psum[r], 2);
    }

    float* sums = reinterpret_cast<float*>(smem + OFF_A(0));  // 128 x 4 floats
    if (tig == 0) {
#pragma unroll
        for (int r = 0; r < 8; r++) {
            const int mf = r >> 1, half = r & 1;
            const int lrow = warp_m * 64 + mf * 16 + half * 8 + g;
            sums[lrow * 4 + warp_n] = psum[r];
        }
    }
    __syncthreads();
    if (tid < M_TILE) {
        float t = sums[tid * 4] + sums[tid * 4 + 1] +
                  sums[tid * 4 + 2] + sums[tid * 4 + 3];
        g_partial[(size_t)blockIdx.x * Mtot + m0 + tid] = t;
    }
}

// ---------------------------------------------------------------------------
// Kernel 3: sum partials, mask, softmax per batch row
// ---------------------------------------------------------------------------
__global__ void softmax_kernel(const int* __restrict__ src_len,
                               float* __restrict__ out) {
    const int b = blockIdx.x;
    const int len = src_len[b];
    const int tid = threadIdx.x;
    __shared__ float sc[Ss];
    __shared__ float red[256];

    float lmax = -3.0e38f;
    for (int s = tid; s < Ss; s += 256) {
        float val = 0.f;
#pragma unroll
        for (int t = 0; t < NTILES; t++)
            val += g_partial[(size_t)t * Mtot + b * Ss + s];
        if (s >= len) val = -3.0e38f;
        sc[s] = val;
        lmax = fmaxf(lmax, val);
    }
    red[tid] = lmax;
    __syncthreads();
    for (int o = 128; o > 0; o >>= 1) {
        if (tid < o) red[tid] = fmaxf(red[tid], red[tid + o]);
        __syncthreads();
    }
    const float gmax = red[0];
    __syncthreads();

    float lsum = 0.f;
    for (int s = tid; s < Ss; s += 256) {
        float e = (s < len) ? __expf(sc[s] - gmax) : 0.f;
        sc[s] = e;
        lsum += e;
    }
    red[tid] = lsum;
    __syncthreads();
    for (int o = 128; o > 0; o >>= 1) {
        if (tid < o) red[tid] += red[tid + o];
        __syncthreads();
    }
    const float inv = 1.f / red[0];
    __syncthreads();
    for (int s = tid; s < Ss; s += 256) out[b * Ss + s] = sc[s] * inv;
}

// ---------------------------------------------------------------------------
extern "C" void kernel_launch(void* const* d_in, const int* in_sizes, int n_in,
                              void* d_out, int out_size) {
    const float* hidden  = (const float*)d_in[0];
    const float* enc     = (const float*)d_in[1];
    const float* W       = (const float*)d_in[2];
    const float* bias    = (const float*)d_in[3];
    const float* v       = (const float*)d_in[4];
    const int*   src_len = (const int*)d_in[5];
    float* out = (float*)d_out;

    cudaFuncSetAttribute(gemm_tanh_kernel,
                         cudaFuncAttributeMaxDynamicSharedMemorySize, SMEM_BYTES);

    econv_kernel<<<16384, 256>>>(enc);
    wconvT_kernel<<<dim3(32, 32), dim3(32, 8)>>>(W);
    prep_kernel<<<dim3(32, 32), 256>>>(hidden, W, bias);
    gemm_tanh_kernel<<<dim3(NTILES, Mtot / M_TILE), 256, SMEM_BYTES>>>(v);
    softmax_kernel<<<Bb, 256>>>(src_len, out);
}